// round 13
// baseline (speedup 1.0000x reference)
#include <cuda_runtime.h>
#include <cuda_fp16.h>
#include <cstdint>

// ===========================================================================
// DNN+LSTM fused, fp16 mma.sync.m16n8k16 (f32 acc).
// KEY CHANGE (R13): 2 CTAs per SM (256 thr, BM=32 each) so one CTA's
// barriers/fills/tail overlap the sibling's HMMAs. k-tile=32, single
// tail-weight buffer, sequential tail stages.
//   Y[B,512] = x @ Wb.T (Wb=[fc1_w; W_ih(i,g,o)[:,:512]])
//   d1=relu(Y0+b); d2=relu(d1@fc2.T+b); d3=d2@fc3.T+b
//   i/g/o = Ygate + d3@Wih[:,512:].T + b; c=sig(i)tanh(g); h=sig(o)tanh(c)
//   out = h @ fc_w.T + fc_b    (f-gate, W_hh, attention dead)
// ===========================================================================

#define NROWS 131072
#define PH 72      // fp16 row pitch (words)
#define PF3 40     // fc3 row pitch (K=64)
#define PB2 196    // preact half2 pitch (words)
#define PA 20      // mainloop A pitch (words), k32 tile

// Mainloop B: fp16 ni-paired fragment layout, 16 tiles x 32KB
__device__ __align__(1024) uint32_t g_WbF[131072];
// Tail weight images (fp16 fragment rows):
//  [0]=fc2(64x72), [4608]=fc3(128x40), [9728]=Wi(128x72), [18944]=Wg,
//  [28160]=Wo, [37376]=fcw  -> 46592 words
__device__ __align__(1024) uint32_t g_WtF[46592];

__device__ __forceinline__ uint32_t h2pack(float a, float b) {
    __half2 h = __floats2half2_rn(a, b);
    return *reinterpret_cast<uint32_t*>(&h);
}
__device__ __forceinline__ void mma16(float* c, uint32_t a0, uint32_t a1,
                                      uint32_t a2, uint32_t a3,
                                      uint32_t b0, uint32_t b1) {
    asm volatile(
        "mma.sync.aligned.m16n8k16.row.col.f32.f16.f16.f32 "
        "{%0,%1,%2,%3},{%4,%5,%6,%7},{%8,%9},{%0,%1,%2,%3};"
        : "+f"(c[0]), "+f"(c[1]), "+f"(c[2]), "+f"(c[3])
        : "r"(a0), "r"(a1), "r"(a2), "r"(a3), "r"(b0), "r"(b1));
}
__device__ __forceinline__ float fsigm(float x) {
    float t = -1.442695041f * x, e, r;
    asm("ex2.approx.f32 %0, %1;" : "=f"(e) : "f"(t));
    float d = 1.0f + e;
    asm("rcp.approx.f32 %0, %1;" : "=f"(r) : "f"(d));
    return r;
}
__device__ __forceinline__ float ftanhA(float x) {
    return fmaf(2.0f, fsigm(2.0f * x), -1.0f);
}
__device__ __forceinline__ uint32_t smem_u32(const void* p) {
    return (uint32_t)__cvta_generic_to_shared(p);
}
__device__ __forceinline__ int kword(int k) {
    int kk = k & 15;
    return (k >> 4) * 8 + ((kk & 7) >> 1) * 2 + ((kk >> 3) & 1);
}

// ---------------------------------------------------------------------------
__global__ void pack_kernel(const float* __restrict__ fc1_w,
                            const float* __restrict__ fc2_w,
                            const float* __restrict__ fc3_w,
                            const float* __restrict__ W_ih,
                            const float* __restrict__ fc_w) {
    int w = blockIdx.x * 256 + threadIdx.x;
    if (w >= 131072 + 46592) return;
    if (w < 131072) {
        // 16 tiles x 8192 words (k32 per tile)
        int tile = w >> 13;
        int rem  = w & 8191;
        int step = rem >> 12;          // 0..1
        int p    = (rem >> 7) & 31;
        int lane = (rem >> 2) & 31;
        int q    = rem & 3;
        int n = (2 * p + (q >> 1)) * 8 + (lane >> 2);
        int k = tile * 32 + step * 16 + 2 * (lane & 3) + 8 * (q & 1);
        float v0, v1;
        if (n < 128) { v0 = fc1_w[n * 512 + k]; v1 = fc1_w[n * 512 + k + 1]; }
        else {
            int sr = (n < 256) ? n - 128 : n;
            v0 = W_ih[(size_t)sr * 640 + k]; v1 = W_ih[(size_t)sr * 640 + k + 1];
        }
        g_WbF[w] = h2pack(v0, v1);
        return;
    }
    int t = w - 131072;
    const float* src; int ww, kc, pitch;
    if (t < 4608)       { int n = t / 72;            ww = t % 72;            kc = 128; src = fc2_w + n * 128; }
    else if (t < 9728)  { int t2 = t - 4608;  int n = t2 / 40; ww = t2 % 40; kc = 64;  src = fc3_w + n * 64; }
    else if (t < 18944) { int t2 = t - 9728;  int n = t2 / 72; ww = t2 % 72; kc = 128; src = W_ih + (size_t)n * 640 + 512; }
    else if (t < 28160) { int t2 = t - 18944; int n = t2 / 72; ww = t2 % 72; kc = 128; src = W_ih + (size_t)(256 + n) * 640 + 512; }
    else if (t < 37376) { int t2 = t - 28160; int n = t2 / 72; ww = t2 % 72; kc = 128; src = W_ih + (size_t)(384 + n) * 640 + 512; }
    else                { int t2 = t - 37376; int n = t2 / 72; ww = t2 % 72; kc = 128; src = fc_w + n * 128; }
    (void)pitch;
    uint32_t val = 0;
    if (ww < (kc >> 1)) {
        int j = ww & 7;
        int k = (ww >> 3) * 16 + (j & 1) * 8 + (j >> 1) * 2;
        val = h2pack(src[k], src[k + 1]);
    }
    g_WtF[t] = val;
}

// ---------------------------------------------------------------------------
// tail GEMM (fp16, permuted rows). 8 warps: twn = warp (NT*8-col group)
// ---------------------------------------------------------------------------
template <int KSTEPS, int NT, int PA_, int PW_>
__device__ __forceinline__ void tgemm_h(const uint32_t* __restrict__ sAa,
                                        const uint32_t* __restrict__ sW,
                                        float tac[2][NT][4],
                                        int twn, int g, int t4) {
#pragma unroll
    for (int s = 0; s < KSTEPS; s++) {
        uint2 alo[2], ahi[2];
#pragma unroll
        for (int mi = 0; mi < 2; mi++) {
            const uint32_t* ap = sAa + (mi * 16 + g) * PA_ + s * 8 + t4 * 2;
            alo[mi] = *(const uint2*)ap;
            ahi[mi] = *(const uint2*)(ap + 8 * PA_);
        }
#pragma unroll
        for (int ni = 0; ni < NT; ni++) {
            int n = (twn * NT + ni) * 8 + g;
            uint2 b = *(const uint2*)(sW + n * PW_ + s * 8 + t4 * 2);
#pragma unroll
            for (int mi = 0; mi < 2; mi++)
                mma16(tac[mi][ni], alo[mi].x, ahi[mi].x, alo[mi].y, ahi[mi].y, b.x, b.y);
        }
    }
}

// ---------------------------------------------------------------------------
// smem per CTA (107520 B):
//  mainloop: sA [0,5120) (2 x 32x20w), sB [5120,70656) (2 x 32KB)
//  Wbuf @70656 (36864)  -- single tail weight buffer, fc2 prefetched
//  tail alias: B0 @0 (32x72w=9216), B2H @9216 (32x196w=25088)
// ---------------------------------------------------------------------------
__global__ void __launch_bounds__(256, 2) fused_kernel(
    const float* __restrict__ x,
    const float* __restrict__ fc1_b, const float* __restrict__ fc2_b,
    const float* __restrict__ fc3_b, const float* __restrict__ b_ih,
    const float* __restrict__ b_hh,  const float* __restrict__ fc_b,
    float* __restrict__ out) {
    extern __shared__ char smem[];
    uint32_t* sAp = (uint32_t*)smem;
    uint32_t* sBp = (uint32_t*)(smem + 5120);
    uint32_t* Wbuf = (uint32_t*)(smem + 70656);
    const uint32_t sbase = smem_u32(smem);
    const uint32_t sB_base = sbase + 5120;
    const uint32_t Wb_base = sbase + 70656;

    const int tid  = threadIdx.x;
    const int lane = tid & 31;
    const int warp = tid >> 5;       // 0..7
    const int g    = lane >> 2;
    const int t4   = lane & 3;
    const int wc   = warp;           // 64-col group in mainloop

    const size_t rowbase = (size_t)blockIdx.x * 32;
    const float* xg = x + rowbase * 512;

    const int r_ = tid >> 3;         // 0..31
    const int c4 = (tid & 7) << 2;   // 0..28

    float acc[2][8][4];
#pragma unroll
    for (int mi = 0; mi < 2; mi++)
#pragma unroll
        for (int ni = 0; ni < 8; ni++)
#pragma unroll
            for (int e = 0; e < 4; e++) acc[mi][ni][e] = 0.0f;

    float4 av;

#define LDA(T) do { av = *(const float4*)(xg + (size_t)r_ * 512 + (T) * 32 + c4); } while (0)

#define STA(S) do { \
    uint32_t* d_ = sAp + (S) * 640 + r_ * PA; \
    d_[kword(c4)]     = h2pack(av.x, av.y); \
    d_[kword(c4 + 2)] = h2pack(av.z, av.w); \
} while (0)

#define CPB_NC(T, S) do { \
    const char* src_ = (const char*)g_WbF + (size_t)(T) * 32768 + tid * 16; \
    uint32_t dst_ = sB_base + (S) * 32768 + tid * 16; \
    _Pragma("unroll") \
    for (int i_ = 0; i_ < 8; i_++) \
        asm volatile("cp.async.cg.shared.global [%0], [%1], 16;" \
                     :: "r"(dst_ + i_ * 4096), "l"(src_ + i_ * 4096)); \
} while (0)

#define FILLW_NC(off_bytes, bytes) do { \
    const char* s_ = (const char*)g_WtF + (off_bytes); \
    for (int o_ = tid * 16; o_ < (bytes); o_ += 4096) \
        asm volatile("cp.async.cg.shared.global [%0], [%1], 16;" \
                     :: "r"(Wb_base + o_), "l"(s_ + o_)); \
} while (0)

#define CPCOMMIT() asm volatile("cp.async.commit_group;" ::: "memory")
#define CPWAIT0()  asm volatile("cp.async.wait_group 0;" ::: "memory")

    // ---- prologue: tile-0 B + A, fc2 prefetch ----
    LDA(0);
    CPB_NC(0, 0);
    FILLW_NC(0, 18432);     // fc2 (word off 0)
    CPCOMMIT();
    STA(0);
    CPWAIT0();
    __syncthreads();

    // ---- mainloop: 16 double-buffered k32 tiles ----
#pragma unroll 1
    for (int t = 0; t < 16; t++) {
        const int cur = t & 1, nxt = cur ^ 1;
        if (t < 15) {
            LDA(t + 1);
            CPB_NC(t + 1, nxt);
            CPCOMMIT();
        }
#pragma unroll
        for (int step = 0; step < 2; step++) {
            uint2 alo[2], ahi[2];
#pragma unroll
            for (int mi = 0; mi < 2; mi++) {
                const uint32_t* ap = sAp + cur * 640 + (mi * 16 + g) * PA + step * 8 + t4 * 2;
                alo[mi] = *(const uint2*)ap;
                ahi[mi] = *(const uint2*)(ap + 8 * PA);
            }
#pragma unroll
            for (int pi = 0; pi < 4; pi++) {
                uint4 bq = *(const uint4*)(sBp + cur * 8192 +
                    ((step * 32 + wc * 4 + pi) * 32 + lane) * 4);
#pragma unroll
                for (int mi = 0; mi < 2; mi++) {
                    mma16(acc[mi][2 * pi],     alo[mi].x, ahi[mi].x, alo[mi].y, ahi[mi].y, bq.x, bq.y);
                    mma16(acc[mi][2 * pi + 1], alo[mi].x, ahi[mi].x, alo[mi].y, ahi[mi].y, bq.z, bq.w);
                }
            }
        }
        if (t < 15) {
            STA(nxt);
            CPWAIT0();
        }
        __syncthreads();
    }

    // ======================= tail =======================
    uint32_t* B0  = (uint32_t*)smem;             // 32 x PH  (fp16 data)
    uint32_t* B2H = (uint32_t*)(smem + 9216);    // 32 x PB2 (half2 preacts)

    const int twn = warp;

    // ---- S0: d1 -> B0 (wc 0,1); gate preacts (half2) -> B2H (wc 2..7) ----
    if (wc < 2) {
#pragma unroll
        for (int mi = 0; mi < 2; mi++)
#pragma unroll
            for (int ni = 0; ni < 8; ni++) {
                int r = mi * 16 + g;
                int cg = wc * 64 + ni * 8 + t4 * 2;
                int w0 = kword(cg);
                B0[r * PH + w0] = h2pack(fmaxf(acc[mi][ni][0] + fc1_b[cg], 0.f),
                                         fmaxf(acc[mi][ni][1] + fc1_b[cg + 1], 0.f));
                B0[(r + 8) * PH + w0] = h2pack(fmaxf(acc[mi][ni][2] + fc1_b[cg], 0.f),
                                               fmaxf(acc[mi][ni][3] + fc1_b[cg + 1], 0.f));
            }
    } else {
#pragma unroll
        for (int mi = 0; mi < 2; mi++)
#pragma unroll
            for (int ni = 0; ni < 8; ni++)
#pragma unroll
                for (int eh = 0; eh < 2; eh++) {
                    int r = mi * 16 + g + eh * 8;
                    int cg = wc * 64 + ni * 8 + t4 * 2;
                    int bi0 = (cg < 256) ? cg - 128 : cg;
                    int pc = cg - 128;
                    B2H[r * PB2 + (pc >> 1)] =
                        h2pack(acc[mi][ni][eh * 2]     + b_ih[bi0]     + b_hh[bi0],
                               acc[mi][ni][eh * 2 + 1] + b_ih[bi0 + 1] + b_hh[bi0 + 1]);
                }
    }
    __syncthreads();

    // ---- G1: d2 = relu(d1 @ fc2.T + b)  [Wbuf = fc2] ----
    {
        float tac1[2][1][4];
#pragma unroll
        for (int mi = 0; mi < 2; mi++)
#pragma unroll
            for (int e = 0; e < 4; e++) tac1[mi][0][e] = 0.f;
        tgemm_h<8, 1, PH, PH>(B0, Wbuf, tac1, twn, g, t4);
        __syncthreads();
        FILLW_NC(18432, 20480);   // fc3 (word 4608)
        CPCOMMIT();
        int c = twn * 8 + t4 * 2;
        int w0 = kword(c);
#pragma unroll
        for (int mi = 0; mi < 2; mi++) {
            int r = mi * 16 + g;
            B0[r * PH + w0] = h2pack(fmaxf(tac1[mi][0][0] + fc2_b[c], 0.f),
                                     fmaxf(tac1[mi][0][1] + fc2_b[c + 1], 0.f));
            B0[(r + 8) * PH + w0] = h2pack(fmaxf(tac1[mi][0][2] + fc2_b[c], 0.f),
                                           fmaxf(tac1[mi][0][3] + fc2_b[c + 1], 0.f));
        }
        CPWAIT0();
        __syncthreads();
    }

    // ---- G2: d3 = d2 @ fc3.T + b  [Wbuf = fc3] ----
    {
        float tac2[2][2][4];
#pragma unroll
        for (int mi = 0; mi < 2; mi++)
#pragma unroll
            for (int ni = 0; ni < 2; ni++)
#pragma unroll
                for (int e = 0; e < 4; e++) tac2[mi][ni][e] = 0.f;
        tgemm_h<4, 2, PH, PF3>(B0, Wbuf, tac2, twn, g, t4);
        __syncthreads();
        FILLW_NC(38912, 36864);   // Wi (word 9728)
        CPCOMMIT();
#pragma unroll
        for (int mi = 0; mi < 2; mi++)
#pragma unroll
            for (int ni = 0; ni < 2; ni++) {
                int r = mi * 16 + g;
                int c = (twn * 2 + ni) * 8 + t4 * 2;
                int w0 = kword(c);
                B0[r * PH + w0] = h2pack(tac2[mi][ni][0] + fc3_b[c],
                                         tac2[mi][ni][1] + fc3_b[c + 1]);
                B0[(r + 8) * PH + w0] = h2pack(tac2[mi][ni][2] + fc3_b[c],
                                               tac2[mi][ni][3] + fc3_b[c + 1]);
            }
        CPWAIT0();
        __syncthreads();
    }

    // ---- Gi: si = sigm(d3 @ Wi.T + preact_i) ----
    float si[2][2][4];
    {
        float tg[2][2][4];
#pragma unroll
        for (int mi = 0; mi < 2; mi++)
#pragma unroll
            for (int ni = 0; ni < 2; ni++)
#pragma unroll
                for (int e = 0; e < 4; e++) tg[mi][ni][e] = 0.f;
        tgemm_h<8, 2, PH, PH>(B0, Wbuf, tg, twn, g, t4);
#pragma unroll
        for (int mi = 0; mi < 2; mi++)
#pragma unroll
            for (int ni = 0; ni < 2; ni++)
#pragma unroll
                for (int eh = 0; eh < 2; eh++) {
                    int r = mi * 16 + g + eh * 8;
                    int wb = r * PB2 + (twn * 2 + ni) * 4 + t4;
                    float2 pv = __half22float2(*(const __half2*)&B2H[wb]);
                    si[mi][ni][eh * 2]     = fsigm(tg[mi][ni][eh * 2]     + pv.x);
                    si[mi][ni][eh * 2 + 1] = fsigm(tg[mi][ni][eh * 2 + 1] + pv.y);
                }
    }
    __syncthreads();
    FILLW_NC(75776, 36864);   // Wg (word 18944)
    CPCOMMIT();
    CPWAIT0();
    __syncthreads();

    // ---- Gg: c = si * tanh(d3 @ Wg.T + preact_g) ----
    float cc[2][2][4];
    {
        float tg[2][2][4];
#pragma unroll
        for (int mi = 0; mi < 2; mi++)
#pragma unroll
            for (int ni = 0; ni < 2; ni++)
#pragma unroll
                for (int e = 0; e < 4; e++) tg[mi][ni][e] = 0.f;
        tgemm_h<8, 2, PH, PH>(B0, Wbuf, tg, twn, g, t4);
#pragma unroll
        for (int mi = 0; mi < 2; mi++)
#pragma unroll
            for (int ni = 0; ni < 2; ni++)
#pragma unroll
                for (int eh = 0; eh < 2; eh++) {
                    int r = mi * 16 + g + eh * 8;
                    int wb = r * PB2 + 64 + (twn * 2 + ni) * 4 + t4;
                    float2 pv = __half22float2(*(const __half2*)&B2H[wb]);
                    cc[mi][ni][eh * 2]     = si[mi][ni][eh * 2]     * ftanhA(tg[mi][ni][eh * 2]     + pv.x);
                    cc[mi][ni][eh * 2 + 1] = si[mi][ni][eh * 2 + 1] * ftanhA(tg[mi][ni][eh * 2 + 1] + pv.y);
                }
    }
    __syncthreads();
    FILLW_NC(112640, 36864);  // Wo (word 28160)
    CPCOMMIT();
    CPWAIT0();
    __syncthreads();

    // ---- Go: h = sigm(d3 @ Wo.T + preact_o) * tanh(c) ----
    float hh[2][2][4];
    {
        float tg[2][2][4];
#pragma unroll
        for (int mi = 0; mi < 2; mi++)
#pragma unroll
            for (int ni = 0; ni < 2; ni++)
#pragma unroll
                for (int e = 0; e < 4; e++) tg[mi][ni][e] = 0.f;
        tgemm_h<8, 2, PH, PH>(B0, Wbuf, tg, twn, g, t4);
#pragma unroll
        for (int mi = 0; mi < 2; mi++)
#pragma unroll
            for (int ni = 0; ni < 2; ni++)
#pragma unroll
                for (int eh = 0; eh < 2; eh++) {
                    int r = mi * 16 + g + eh * 8;
                    int wb = r * PB2 + 128 + (twn * 2 + ni) * 4 + t4;
                    float2 pv = __half22float2(*(const __half2*)&B2H[wb]);
                    hh[mi][ni][eh * 2]     = fsigm(tg[mi][ni][eh * 2]     + pv.x) * ftanhA(cc[mi][ni][eh * 2]);
                    hh[mi][ni][eh * 2 + 1] = fsigm(tg[mi][ni][eh * 2 + 1] + pv.y) * ftanhA(cc[mi][ni][eh * 2 + 1]);
                }
    }
    __syncthreads();
    FILLW_NC(149504, 36864);  // fcw (word 37376)
    CPCOMMIT();
    // store h -> B0 while fcw streams in
#pragma unroll
    for (int mi = 0; mi < 2; mi++)
#pragma unroll
        for (int ni = 0; ni < 2; ni++) {
            int r = mi * 16 + g;
            int c = (twn * 2 + ni) * 8 + t4 * 2;
            int w0 = kword(c);
            B0[r * PH + w0]       = h2pack(hh[mi][ni][0], hh[mi][ni][1]);
            B0[(r + 8) * PH + w0] = h2pack(hh[mi][ni][2], hh[mi][ni][3]);
        }
    CPWAIT0();
    __syncthreads();

    // ---- G4: out = h @ fc_w.T + fc_b ----
    {
        float tac2[2][2][4];
#pragma unroll
        for (int mi = 0; mi < 2; mi++)
#pragma unroll
            for (int ni = 0; ni < 2; ni++)
#pragma unroll
                for (int e = 0; e < 4; e++) tac2[mi][ni][e] = 0.f;
        tgemm_h<8, 2, PH, PH>(B0, Wbuf, tac2, twn, g, t4);
#pragma unroll
        for (int mi = 0; mi < 2; mi++)
#pragma unroll
            for (int ni = 0; ni < 2; ni++) {
                int r = mi * 16 + g;
                int c = (twn * 2 + ni) * 8 + t4 * 2;
                *(float2*)(out + (rowbase + r) * 128 + c) =
                    make_float2(tac2[mi][ni][0] + fc_b[c], tac2[mi][ni][1] + fc_b[c + 1]);
                *(float2*)(out + (rowbase + r + 8) * 128 + c) =
                    make_float2(tac2[mi][ni][2] + fc_b[c], tac2[mi][ni][3] + fc_b[c + 1]);
            }
    }
#undef LDA
#undef STA
#undef CPB_NC
#undef FILLW_NC
#undef CPCOMMIT
#undef CPWAIT0
}

// ---------------------------------------------------------------------------
extern "C" void kernel_launch(void* const* d_in, const int* in_sizes, int n_in,
                              void* d_out, int out_size) {
    const float* x     = (const float*)d_in[0];
    const float* fc1_w = (const float*)d_in[1];
    const float* fc1_b = (const float*)d_in[2];
    const float* fc2_w = (const float*)d_in[3];
    const float* fc2_b = (const float*)d_in[4];
    const float* fc3_w = (const float*)d_in[5];
    const float* fc3_b = (const float*)d_in[6];
    const float* W_ih  = (const float*)d_in[7];
    // d_in[8] = W_hh (dead: h_prev == 0)
    const float* b_ih  = (const float*)d_in[9];
    const float* b_hh  = (const float*)d_in[10];
    // d_in[11..12] = attn_w, attn_b (dead: softmax over length-1 seq == 1)
    const float* fc_w  = (const float*)d_in[13];
    const float* fc_b  = (const float*)d_in[14];
    float* out = (float*)d_out;

    const int smem = 107520;
    cudaFuncSetAttribute(fused_kernel, cudaFuncAttributeMaxDynamicSharedMemorySize, smem);

    pack_kernel<<<694, 256>>>(fc1_w, fc2_w, fc3_w, W_ih, fc_w);
    fused_kernel<<<NROWS / 32, 256, smem>>>(x, fc1_b, fc2_b, fc3_b,
                                            b_ih, b_hh, fc_b, out);
}